// round 11
// baseline (speedup 1.0000x reference)
#include <cuda_runtime.h>

typedef unsigned long long ull;
typedef unsigned int uint;

#define T_STEPS 2048
#define B_ROWS  256
#define HID     128
#define NG      512

// ---------------- scratch (device globals: allocation-free) ----------------
__device__ float g_hseq[(size_t)T_STEPS * B_ROWS * HID];   // 256 MB
__device__ float g_xg[(size_t)T_STEPS * B_ROWS * NG];      // 1 GB
__device__ float g_hT[B_ROWS * HID];

// ---------------- helpers ----------------
__device__ __forceinline__ ull pk2(float lo, float hi){
    ull r; asm("mov.b64 %0,{%1,%2};" : "=l"(r) : "f"(lo), "f"(hi)); return r;
}
__device__ __forceinline__ ull ffma2(ull a, ull b, ull c){
    ull d; asm("fma.rn.f32x2 %0,%1,%2,%3;" : "=l"(d) : "l"(a), "l"(b), "l"(c)); return d;
}
__device__ __forceinline__ float2 unpk(ull v){
    float2 r; asm("mov.b64 {%0,%1},%2;" : "=f"(r.x), "=f"(r.y) : "l"(v)); return r;
}
__device__ __forceinline__ float tanha(float x){
    float y; asm("tanh.approx.f32 %0,%1;" : "=f"(y) : "f"(x)); return y;
}
__device__ __forceinline__ float siga(float x){            // sigmoid via MUFU.TANH
    return fmaf(0.5f, tanha(0.5f * x), 0.5f);
}

// ================= recurrent kernel v5: 512 threads, 1 gate row/thread =========
// 128 CTAs x 512 threads. CTA b owns batch rows 2b, 2b+1.
// Thread tid owns gate row j=tid (i:0-127, f:128-255, g:256-383, o:384-511)
// and computes its preactivation for BOTH batch rows (2 accumulators).
// Whh cols [0,80) in regs (40 ull = 80 regs), cols [80,128) in SMEM (12 float4).
// Gate exchange via sg smem; cell update by tid<256 (s=tid>>7, u=tid&127).
constexpr int KREGP = 40;                  // f32x2 pairs in regs per gate row
constexpr int KSM4  = 12;                  // float4 tail chunks (48 cols)
constexpr int WS_F  = KSM4 * NG * 4;       // 24576 floats (98304 B)
constexpr int REC_SMEM_BASE = (WS_F + 2*NG + 2*HID) * 4;           // 103424
constexpr int REC_SMEM0     = REC_SMEM_BASE + 2 * T_STEPS * 4;     // 119808

template<int MODE>   // 0: layer0 (x folded, writes hseq) 1: mid 2: last (writes hT)
__global__ void __launch_bounds__(512, 1)
lstm_rec(const float* __restrict__ xin,
         const float* __restrict__ wih,
         const float* __restrict__ bih,
         const float* __restrict__ bhh,
         const float* __restrict__ Whh)
{
    extern __shared__ float sm[];
    float* ws = sm;                        // [KSM4][NG] weight tail (16B/slot)
    float* sg = sm + WS_F;                 // [2 batch][NG] raw gate activations
    float* sh = sg + 2*NG;                 // [2 batch][HID] hidden state
    float* sx = sh + 2*HID;                // MODE0: [2][T] input cache

    const int tid = threadIdx.x;           // gate row j = tid
    const int r0 = blockIdx.x * 2;

    // ---- one-time weight load: 80 cols -> regs, 48 cols -> smem ----
    ull w[KREGP];
    {
        const float* p = Whh + (size_t)tid * HID;
        #pragma unroll
        for (int q = 0; q < KREGP; q++) w[q] = *(const ull*)(p + 2*q);
        #pragma unroll
        for (int q = 0; q < KSM4; q++)
            *(float4*)&ws[(q*NG + tid)*4] = *(const float4*)(p + 2*KREGP + 4*q);
    }
    float wi = 0.f, bb = 0.f;
    if (MODE == 0){
        wi = wih[tid];
        bb = bih[tid] + bhh[tid];
        for (int i = tid; i < 2*T_STEPS; i += 512){
            int row = i >> 11, t = i & (T_STEPS-1);
            sx[i] = xin[(size_t)(r0 + row) * T_STEPS + t];
        }
    }
    if (tid < 2*HID) sh[tid] = 0.f;
    float cc = 0.f;                        // cell state of (s=tid>>7, u=tid&127), tid<256
    __syncthreads();

    // prefetch t=0 gate inputs (batch 0 and 1 for row tid)
    float nx0, nx1;
    if (MODE != 0){
        const float* xq = g_xg + (size_t)r0 * NG + tid;
        nx0 = __ldcs(xq); nx1 = __ldcs(xq + NG);
    }

    // activation selector: g rows (256..383) use tanh, others sigmoid
    const bool is_g = (tid >= 2*HID) && (tid < 3*HID);

    #pragma unroll 1
    for (int t = 0; t < T_STEPS; t++){
        float in0, in1;
        if (MODE == 0){
            in0 = fmaf(sx[t], wi, bb);
            in1 = fmaf(sx[T_STEPS + t], wi, bb);
        } else {
            in0 = nx0; in1 = nx1;
            int tn = (t + 1 < T_STEPS) ? t + 1 : t;
            const float* xq = g_xg + ((size_t)tn * B_ROWS + r0) * NG + tid;
            nx0 = __ldcs(xq); nx1 = __ldcs(xq + NG);
        }
        ull a0 = pk2(in0, 0.f), a1 = pk2(in1, 0.f);

        const ulonglong2* h0 = (const ulonglong2*)sh;          // batch 0 (32 x 16B)
        const ulonglong2* h1 = h0 + HID/4;                     // batch 1
        #pragma unroll
        for (int q = 0; q < KREGP/2; q++){
            ulonglong2 p0 = h0[q], p1 = h1[q];
            a0 = ffma2(w[2*q],   p0.x, a0);
            a0 = ffma2(w[2*q+1], p0.y, a0);
            a1 = ffma2(w[2*q],   p1.x, a1);
            a1 = ffma2(w[2*q+1], p1.y, a1);
        }
        // tail: cols 80..127 from smem (one 16B slot = 4 cols per q)
        const ulonglong2* wt = (const ulonglong2*)ws;
        #pragma unroll
        for (int q = 0; q < KSM4; q++){
            ulonglong2 v  = wt[q*NG + tid];
            ulonglong2 q0 = h0[KREGP/2 + q];
            ulonglong2 q1 = h1[KREGP/2 + q];
            a0 = ffma2(v.x, q0.x, a0); a0 = ffma2(v.y, q0.y, a0);
            a1 = ffma2(v.x, q1.x, a1); a1 = ffma2(v.y, q1.y, a1);
        }
        float2 s0 = unpk(a0), s1 = unpk(a1);
        float g0 = s0.x + s0.y, g1 = s1.x + s1.y;
        if (is_g){ g0 = tanha(g0); g1 = tanha(g1); }
        else     { g0 = siga(g0);  g1 = siga(g1); }
        sg[tid]      = g0;
        sg[NG + tid] = g1;
        __syncthreads();

        if (tid < 256){
            int s = tid >> 7, u = tid & 127;
            const float* sgr = sg + s * NG;
            float iv = sgr[u], fv = sgr[HID+u], gv = sgr[2*HID+u], ov = sgr[3*HID+u];
            cc = fmaf(fv, cc, iv * gv);
            float hv = ov * tanha(cc);
            sh[s * HID + u] = hv;
            if (MODE != 2){
                g_hseq[((size_t)t * B_ROWS + r0 + s) * HID + u] = hv;
            } else if (t == T_STEPS - 1){
                g_hT[(size_t)(r0 + s) * HID + u] = hv;
            }
        }
        __syncthreads();
    }
}

// ================= input-projection GEMM v3 (frozen) =================
constexpr int M_TILES   = (T_STEPS * B_ROWS) / 128;     // 4096
constexpr int GRID_X    = 37;
constexpr int A_TILE_F  = 128 * 128;
constexpr int BQ_F4     = 32 * 129;
constexpr int GEMM_SMEM = (2 * A_TILE_F) * 4 + BQ_F4 * 16;   // 197120 B

__global__ void __launch_bounds__(256, 1)
gemm_xg(const float* __restrict__ W,
        const float* __restrict__ ba,
        const float* __restrict__ bb)
{
    extern __shared__ float sm[];
    float*  As = sm;                             // [2][128][128]
    float4* Bq = (float4*)(sm + 2 * A_TILE_F);   // [32][129]

    const int tid = threadIdx.x;
    const int tx = tid & 15, ty = tid >> 4;
    const int n0 = blockIdx.y * 128;

    #pragma unroll
    for (int i = 0; i < 16; i++){
        int idx = tid + i * 256;                  // over [128 n][32 k4]
        int n = idx >> 5, k4 = idx & 31;
        Bq[k4 * 129 + n] = *(const float4*)&W[(size_t)(n0 + n) * HID + 4 * k4];
    }

    float bias[8];
    #pragma unroll
    for (int c = 0; c < 8; c++){
        int n = n0 + tx + 16*c;
        bias[c] = __ldg(ba + n) + __ldg(bb + n);
    }

    uint sA = (uint)__cvta_generic_to_shared(As);
    auto issue = [&](int mt, int buf){
        const float* src = g_hseq + (size_t)mt * A_TILE_F;
        uint dst = sA + buf * (A_TILE_F * 4);
        #pragma unroll
        for (int i = 0; i < 16; i++){
            int idx = tid + i * 256;
            asm volatile("cp.async.cg.shared.global [%0], [%1], 16;\n"
                         :: "r"(dst + idx * 16), "l"(src + idx * 4));
        }
        asm volatile("cp.async.commit_group;\n" ::: "memory");
    };

    int mt = blockIdx.x;
    if (mt < M_TILES) issue(mt, 0);
    int buf = 0;

    #pragma unroll 1
    for (; mt < M_TILES; mt += GRID_X){
        int nxt = mt + GRID_X;
        if (nxt < M_TILES) issue(nxt, buf ^ 1);
        if (nxt < M_TILES) asm volatile("cp.async.wait_group 1;\n" ::: "memory");
        else               asm volatile("cp.async.wait_group 0;\n" ::: "memory");
        __syncthreads();

        const float* Ab = As + buf * A_TILE_F;
        ull acc[8][8];
        #pragma unroll
        for (int r = 0; r < 8; r++)
            #pragma unroll
            for (int c = 0; c < 8; c++) acc[r][c] = 0ULL;

        #pragma unroll 1
        for (int kp2 = 0; kp2 < 32; kp2++){
            ulonglong2 a2[8], b2[8];
            #pragma unroll
            for (int r = 0; r < 8; r++)
                a2[r] = *(const ulonglong2*)&Ab[(ty*8 + r) * 128 + 4*kp2];
            #pragma unroll
            for (int c = 0; c < 8; c++)
                b2[c] = ((const ulonglong2*)Bq)[kp2 * 129 + tx + 16*c];
            #pragma unroll
            for (int r = 0; r < 8; r++)
                #pragma unroll
                for (int c = 0; c < 8; c++){
                    acc[r][c] = ffma2(a2[r].x, b2[c].x, acc[r][c]);
                    acc[r][c] = ffma2(a2[r].y, b2[c].y, acc[r][c]);
                }
        }

        #pragma unroll
        for (int c = 0; c < 8; c++){
            int n = tx + 16*c;
            #pragma unroll
            for (int r = 0; r < 8; r++){
                float2 v = unpk(acc[r][c]);
                g_xg[((size_t)mt * 128 + ty*8 + r) * NG + n0 + n] = v.x + v.y + bias[c];
            }
        }
        __syncthreads();
        buf ^= 1;
    }
}

// ================= FC head =================
__global__ void head_kernel(const float* __restrict__ w1, const float* __restrict__ b1,
                            const float* __restrict__ w2, const float* __restrict__ b2,
                            float* __restrict__ out)
{
    __shared__ float z[64];
    int b = blockIdx.x, u = threadIdx.x;
    const float* h = g_hT + (size_t)b * HID;
    float acc = b1[u];
    const float* w = w1 + (size_t)u * HID;
    #pragma unroll 4
    for (int k = 0; k < HID; k++) acc = fmaf(w[k], h[k], acc);
    z[u] = fmaxf(acc, 0.f);
    __syncthreads();
    if (u < 5){
        float a2 = b2[u];
        const float* ww = w2 + u * 64;
        #pragma unroll 4
        for (int k = 0; k < 64; k++) a2 = fmaf(ww[k], z[k], a2);
        out[b * 5 + u] = a2;
    }
}

// ================= launch =================
extern "C" void kernel_launch(void* const* d_in, const int* in_sizes, int n_in,
                              void* d_out, int out_size)
{
    const float* x    = (const float*)d_in[0];
    const float* Wih0 = (const float*)d_in[1];
    const float* Whh0 = (const float*)d_in[2];
    const float* bih0 = (const float*)d_in[3];
    const float* bhh0 = (const float*)d_in[4];
    const float* Wih1 = (const float*)d_in[5];
    const float* Whh1 = (const float*)d_in[6];
    const float* bih1 = (const float*)d_in[7];
    const float* bhh1 = (const float*)d_in[8];
    const float* Wih2 = (const float*)d_in[9];
    const float* Whh2 = (const float*)d_in[10];
    const float* bih2 = (const float*)d_in[11];
    const float* bhh2 = (const float*)d_in[12];
    const float* fc1w = (const float*)d_in[13];
    const float* fc1b = (const float*)d_in[14];
    const float* fc2w = (const float*)d_in[15];
    const float* fc2b = (const float*)d_in[16];
    float* out = (float*)d_out;

    cudaFuncSetAttribute(lstm_rec<0>, cudaFuncAttributeMaxDynamicSharedMemorySize, REC_SMEM0);
    cudaFuncSetAttribute(lstm_rec<1>, cudaFuncAttributeMaxDynamicSharedMemorySize, REC_SMEM_BASE);
    cudaFuncSetAttribute(lstm_rec<2>, cudaFuncAttributeMaxDynamicSharedMemorySize, REC_SMEM_BASE);
    cudaFuncSetAttribute(gemm_xg,     cudaFuncAttributeMaxDynamicSharedMemorySize, GEMM_SMEM);

    lstm_rec<0><<<128, 512, REC_SMEM0>>>(x, Wih0, bih0, bhh0, Whh0);
    gemm_xg<<<dim3(GRID_X, 4), 256, GEMM_SMEM>>>(Wih1, bih1, bhh1);
    lstm_rec<1><<<128, 512, REC_SMEM_BASE>>>(nullptr, nullptr, nullptr, nullptr, Whh1);
    gemm_xg<<<dim3(GRID_X, 4), 256, GEMM_SMEM>>>(Wih2, bih2, bhh2);
    lstm_rec<2><<<128, 512, REC_SMEM_BASE>>>(nullptr, nullptr, nullptr, nullptr, Whh2);
    head_kernel<<<B_ROWS, 64>>>(fc1w, fc1b, fc2w, fc2b, out);
}

// round 13
// speedup vs baseline: 1.1793x; 1.1793x over previous
#include <cuda_runtime.h>

typedef unsigned long long ull;
typedef unsigned int uint;

#define T_STEPS 2048
#define B_ROWS  256
#define HID     128
#define NG      512

// ---------------- scratch (device globals: allocation-free) ----------------
__device__ float g_hseq[(size_t)T_STEPS * B_ROWS * HID];   // 256 MB
__device__ float g_xg[(size_t)T_STEPS * B_ROWS * NG];      // 1 GB
__device__ float g_hT[B_ROWS * HID];

// ---------------- helpers ----------------
__device__ __forceinline__ ull pk2(float lo, float hi){
    ull r; asm("mov.b64 %0,{%1,%2};" : "=l"(r) : "f"(lo), "f"(hi)); return r;
}
__device__ __forceinline__ ull ffma2(ull a, ull b, ull c){
    ull d; asm("fma.rn.f32x2 %0,%1,%2,%3;" : "=l"(d) : "l"(a), "l"(b), "l"(c)); return d;
}
__device__ __forceinline__ float2 unpk(ull v){
    float2 r; asm("mov.b64 {%0,%1},%2;" : "=f"(r.x), "=f"(r.y) : "l"(v)); return r;
}
__device__ __forceinline__ float sigf(float x){
    return __fdividef(1.f, 1.f + __expf(-x));
}
__device__ __forceinline__ float tanhf_(float x){
    return 1.f - 2.f * __fdividef(1.f, __expf(2.f * x) + 1.f);
}

// ================= recurrent kernel (R5 structure, KREGP=44) =================
// 128 CTAs x 256 threads. CTA b owns batch rows 2b, 2b+1.
// Thread tid owns gate rows j0=tid (i|f) and j1=tid+256 (g|o).
// Whh cols [0,88) in regs (44 ull/row = 176 regs), cols [88,128) in SMEM.
constexpr int KREGP = 44;
constexpr int KSM4  = 10;
constexpr int REC_SMEM_BASE = (KSM4*NG*4 + 2*HID + 2*NG) * 4;          // 86528
constexpr int REC_SMEM0     = REC_SMEM_BASE + 2*T_STEPS*4;             // 102912

template<int MODE>   // 0: layer0 (x folded, writes hseq) 1: mid 2: last (writes hT)
__global__ void __launch_bounds__(256, 1)
lstm_rec(const float* __restrict__ xin,
         const float* __restrict__ wih,
         const float* __restrict__ bih,
         const float* __restrict__ bhh,
         const float* __restrict__ Whh)
{
    extern __shared__ float sm[];
    float4* ws = (float4*)sm;             // [KSM4][NG] weight tail
    float*  sh = sm + KSM4*NG*4;          // [2][HID] hidden state
    float*  sg = sh + 2*HID;              // [2][NG]  activated gates
    float*  sx = sg + 2*NG;               // MODE0: [2][T] input cache

    const int tid = threadIdx.x;
    const int j0 = tid, j1 = tid + 256;
    const int r0 = blockIdx.x * 2;

    // one-time weight load: 88 cols -> regs, 40 cols -> smem
    ull w0[KREGP], w1[KREGP];
    {
        const float* p0 = Whh + (size_t)j0 * HID;
        const float* p1 = Whh + (size_t)j1 * HID;
        #pragma unroll
        for (int p = 0; p < KREGP; p++){
            w0[p] = *(const ull*)(p0 + 2*p);
            w1[p] = *(const ull*)(p1 + 2*p);
        }
        #pragma unroll
        for (int q = 0; q < KSM4; q++){
            ws[q*NG + j0] = *(const float4*)(p0 + 2*KREGP + 4*q);
            ws[q*NG + j1] = *(const float4*)(p1 + 2*KREGP + 4*q);
        }
    }
    float wi0 = 0.f, wi1 = 0.f, bb0 = 0.f, bb1 = 0.f;
    if (MODE == 0){
        wi0 = wih[j0]; wi1 = wih[j1];
        bb0 = bih[j0] + bhh[j0]; bb1 = bih[j1] + bhh[j1];
        for (int i = tid; i < 2*T_STEPS; i += 256){
            int row = i >> 11, t = i & (T_STEPS-1);
            sx[i] = xin[(size_t)(r0 + row) * T_STEPS + t];
        }
    }
    if (tid < HID){ sh[tid] = 0.f; sh[HID + tid] = 0.f; }
    float c0 = 0.f, c1 = 0.f;
    __syncthreads();

    // prefetch t=0 gate inputs
    float nx00, nx01, nx10, nx11;
    if (MODE != 0){
        const float* xg = g_xg + (size_t)r0 * NG;
        nx00 = __ldcs(xg + j0);      nx10 = __ldcs(xg + j1);
        nx01 = __ldcs(xg + NG + j0); nx11 = __ldcs(xg + NG + j1);
    }

    #pragma unroll 1
    for (int t = 0; t < T_STEPS; t++){
        float in00, in01, in10, in11;
        if (MODE == 0){
            float xv0 = sx[t], xv1 = sx[T_STEPS + t];
            in00 = fmaf(xv0, wi0, bb0); in01 = fmaf(xv1, wi0, bb0);
            in10 = fmaf(xv0, wi1, bb1); in11 = fmaf(xv1, wi1, bb1);
        } else {
            in00 = nx00; in01 = nx01; in10 = nx10; in11 = nx11;
            int tn = (t + 1 < T_STEPS) ? t + 1 : t;
            const float* xgn = g_xg + ((size_t)tn * B_ROWS + r0) * NG;
            nx00 = __ldcs(xgn + j0);      nx10 = __ldcs(xgn + j1);
            nx01 = __ldcs(xgn + NG + j0); nx11 = __ldcs(xgn + NG + j1);
        }
        ull a00 = pk2(in00, 0.f), a01 = pk2(in01, 0.f);
        ull a10 = pk2(in10, 0.f), a11 = pk2(in11, 0.f);

        const ulonglong2* h0 = (const ulonglong2*)sh;
        const ulonglong2* h1 = (const ulonglong2*)(sh + HID);
        #pragma unroll
        for (int p = 0; p < KREGP/2; p++){
            ulonglong2 hp0 = h0[p], hp1 = h1[p];
            a00 = ffma2(w0[2*p],   hp0.x, a00);
            a00 = ffma2(w0[2*p+1], hp0.y, a00);
            a01 = ffma2(w0[2*p],   hp1.x, a01);
            a01 = ffma2(w0[2*p+1], hp1.y, a01);
            a10 = ffma2(w1[2*p],   hp0.x, a10);
            a10 = ffma2(w1[2*p+1], hp0.y, a10);
            a11 = ffma2(w1[2*p],   hp1.x, a11);
            a11 = ffma2(w1[2*p+1], hp1.y, a11);
        }
        #pragma unroll
        for (int q = 0; q < KSM4; q++){
            float4 v0 = ws[q*NG + j0];
            float4 v1 = ws[q*NG + j1];
            ulonglong2 hq0 = h0[KREGP/2 + q];
            ulonglong2 hq1 = h1[KREGP/2 + q];
            ull w0a = pk2(v0.x, v0.y), w0b = pk2(v0.z, v0.w);
            ull w1a = pk2(v1.x, v1.y), w1b = pk2(v1.z, v1.w);
            a00 = ffma2(w0a, hq0.x, a00); a00 = ffma2(w0b, hq0.y, a00);
            a01 = ffma2(w0a, hq1.x, a01); a01 = ffma2(w0b, hq1.y, a01);
            a10 = ffma2(w1a, hq0.x, a10); a10 = ffma2(w1b, hq0.y, a10);
            a11 = ffma2(w1a, hq1.x, a11); a11 = ffma2(w1b, hq1.y, a11);
        }
        float2 f00 = unpk(a00), f01 = unpk(a01), f10 = unpk(a10), f11 = unpk(a11);
        float g00 = f00.x + f00.y, g01 = f01.x + f01.y;
        float g10 = f10.x + f10.y, g11 = f11.x + f11.y;
        g00 = sigf(g00); g01 = sigf(g01);
        if (tid < 128){ g10 = tanhf_(g10); g11 = tanhf_(g11); }
        else          { g10 = sigf(g10);   g11 = sigf(g11);  }
        sg[j0]      = g00; sg[j1]      = g10;
        sg[NG + j0] = g01; sg[NG + j1] = g11;
        __syncthreads();
        {
            int row = tid >> 7, u = tid & 127;
            float* cc = (tid < 128) ? &c0 : &c1;
            const float* sgr = sg + row * NG;
            float iv = sgr[u], fv = sgr[HID+u], gv = sgr[2*HID+u], ov = sgr[3*HID+u];
            *cc = fmaf(fv, *cc, iv * gv);
            float hv = ov * tanhf_(*cc);
            sh[row * HID + u] = hv;
            if (MODE != 2){
                g_hseq[((size_t)t * B_ROWS + r0 + row) * HID + u] = hv;
            } else if (t == T_STEPS - 1){
                g_hT[(size_t)(r0 + row) * HID + u] = hv;
            }
        }
        __syncthreads();
    }
}

// ================= input-projection GEMM v4: 64-row tiles, 2 CTAs/SM ==========
// C(M=524288,512) = hseq(M,128) @ W^T + bias. Persistent grid (74,4).
// Per CTA: M-tile 64 rows. B resident in smem as [k4][n] float4 (pad 129).
// A tiles natural [m][k], double-buffered cp.async. 2 CTAs/SM -> 4 warps/SMSP.
constexpr int M_TILES   = (T_STEPS * B_ROWS) / 64;      // 8192
constexpr int GRID_X    = 74;
constexpr int A_TILE_F  = 64 * 128;                     // 8192 floats (32KB)
constexpr int BQ_F4     = 32 * 129;
constexpr int GEMM_SMEM = (2 * A_TILE_F) * 4 + BQ_F4 * 16;   // 98624 B

__global__ void __launch_bounds__(256, 2)
gemm_xg(const float* __restrict__ W,
        const float* __restrict__ ba,
        const float* __restrict__ bb)
{
    extern __shared__ float sm[];
    float*  As = sm;                             // [2][64][128]
    float4* Bq = (float4*)(sm + 2 * A_TILE_F);   // [32][129]

    const int tid = threadIdx.x;
    const int tx = tid & 15, ty = tid >> 4;      // ty 0..15 -> 4 rows each
    const int n0 = blockIdx.y * 128;

    #pragma unroll
    for (int i = 0; i < 16; i++){
        int idx = tid + i * 256;                  // over [128 n][32 k4]
        int n = idx >> 5, k4 = idx & 31;
        Bq[k4 * 129 + n] = *(const float4*)&W[(size_t)(n0 + n) * HID + 4 * k4];
    }

    float bias[8];
    #pragma unroll
    for (int c = 0; c < 8; c++){
        int n = n0 + tx + 16*c;
        bias[c] = __ldg(ba + n) + __ldg(bb + n);
    }

    uint sA = (uint)__cvta_generic_to_shared(As);
    auto issue = [&](int mt, int buf){
        const float* src = g_hseq + (size_t)mt * A_TILE_F;
        uint dst = sA + buf * (A_TILE_F * 4);
        #pragma unroll
        for (int i = 0; i < 8; i++){
            int idx = tid + i * 256;              // 2048 float4 chunks
            asm volatile("cp.async.cg.shared.global [%0], [%1], 16;\n"
                         :: "r"(dst + idx * 16), "l"(src + idx * 4));
        }
        asm volatile("cp.async.commit_group;\n" ::: "memory");
    };

    int mt = blockIdx.x;
    if (mt < M_TILES) issue(mt, 0);
    int buf = 0;

    #pragma unroll 1
    for (; mt < M_TILES; mt += GRID_X){
        int nxt = mt + GRID_X;
        if (nxt < M_TILES) issue(nxt, buf ^ 1);
        if (nxt < M_TILES) asm volatile("cp.async.wait_group 1;\n" ::: "memory");
        else               asm volatile("cp.async.wait_group 0;\n" ::: "memory");
        __syncthreads();

        const float* Ab = As + buf * A_TILE_F;
        ull acc[4][8];
        #pragma unroll
        for (int r = 0; r < 4; r++)
            #pragma unroll
            for (int c = 0; c < 8; c++) acc[r][c] = 0ULL;

        #pragma unroll 2
        for (int kp2 = 0; kp2 < 32; kp2++){
            ulonglong2 a2[4], b2[8];
            #pragma unroll
            for (int r = 0; r < 4; r++)
                a2[r] = *(const ulonglong2*)&Ab[(ty*4 + r) * 128 + 4*kp2];
            #pragma unroll
            for (int c = 0; c < 8; c++)
                b2[c] = ((const ulonglong2*)Bq)[kp2 * 129 + tx + 16*c];
            #pragma unroll
            for (int r = 0; r < 4; r++)
                #pragma unroll
                for (int c = 0; c < 8; c++){
                    acc[r][c] = ffma2(a2[r].x, b2[c].x, acc[r][c]);
                    acc[r][c] = ffma2(a2[r].y, b2[c].y, acc[r][c]);
                }
        }

        #pragma unroll
        for (int c = 0; c < 8; c++){
            int n = tx + 16*c;
            #pragma unroll
            for (int r = 0; r < 4; r++){
                float2 v = unpk(acc[r][c]);
                g_xg[((size_t)mt * 64 + ty*4 + r) * NG + n0 + n] = v.x + v.y + bias[c];
            }
        }
        __syncthreads();
        buf ^= 1;
    }
}

// ================= FC head =================
__global__ void head_kernel(const float* __restrict__ w1, const float* __restrict__ b1,
                            const float* __restrict__ w2, const float* __restrict__ b2,
                            float* __restrict__ out)
{
    __shared__ float z[64];
    int b = blockIdx.x, u = threadIdx.x;
    const float* h = g_hT + (size_t)b * HID;
    float acc = b1[u];
    const float* w = w1 + (size_t)u * HID;
    #pragma unroll 4
    for (int k = 0; k < HID; k++) acc = fmaf(w[k], h[k], acc);
    z[u] = fmaxf(acc, 0.f);
    __syncthreads();
    if (u < 5){
        float a2 = b2[u];
        const float* ww = w2 + u * 64;
        #pragma unroll 4
        for (int k = 0; k < 64; k++) a2 = fmaf(ww[k], z[k], a2);
        out[b * 5 + u] = a2;
    }
}

// ================= launch =================
extern "C" void kernel_launch(void* const* d_in, const int* in_sizes, int n_in,
                              void* d_out, int out_size)
{
    const float* x    = (const float*)d_in[0];
    const float* Wih0 = (const float*)d_in[1];
    const float* Whh0 = (const float*)d_in[2];
    const float* bih0 = (const float*)d_in[3];
    const float* bhh0 = (const float*)d_in[4];
    const float* Wih1 = (const float*)d_in[5];
    const float* Whh1 = (const float*)d_in[6];
    const float* bih1 = (const float*)d_in[7];
    const float* bhh1 = (const float*)d_in[8];
    const float* Wih2 = (const float*)d_in[9];
    const float* Whh2 = (const float*)d_in[10];
    const float* bih2 = (const float*)d_in[11];
    const float* bhh2 = (const float*)d_in[12];
    const float* fc1w = (const float*)d_in[13];
    const float* fc1b = (const float*)d_in[14];
    const float* fc2w = (const float*)d_in[15];
    const float* fc2b = (const float*)d_in[16];
    float* out = (float*)d_out;

    cudaFuncSetAttribute(lstm_rec<0>, cudaFuncAttributeMaxDynamicSharedMemorySize, REC_SMEM0);
    cudaFuncSetAttribute(lstm_rec<1>, cudaFuncAttributeMaxDynamicSharedMemorySize, REC_SMEM_BASE);
    cudaFuncSetAttribute(lstm_rec<2>, cudaFuncAttributeMaxDynamicSharedMemorySize, REC_SMEM_BASE);
    cudaFuncSetAttribute(gemm_xg,     cudaFuncAttributeMaxDynamicSharedMemorySize, GEMM_SMEM);

    lstm_rec<0><<<128, 256, REC_SMEM0>>>(x, Wih0, bih0, bhh0, Whh0);
    gemm_xg<<<dim3(GRID_X, 4), 256, GEMM_SMEM>>>(Wih1, bih1, bhh1);
    lstm_rec<1><<<128, 256, REC_SMEM_BASE>>>(nullptr, nullptr, nullptr, nullptr, Whh1);
    gemm_xg<<<dim3(GRID_X, 4), 256, GEMM_SMEM>>>(Wih2, bih2, bhh2);
    lstm_rec<2><<<128, 256, REC_SMEM_BASE>>>(nullptr, nullptr, nullptr, nullptr, Whh2);
    head_kernel<<<B_ROWS, 64>>>(fc1w, fc1b, fc2w, fc2b, out);
}

// round 14
// speedup vs baseline: 1.2067x; 1.0232x over previous
#include <cuda_runtime.h>

typedef unsigned long long ull;
typedef unsigned int uint;

#define T_STEPS 2048
#define B_ROWS  256
#define HID     128
#define NG      512

// ---------------- scratch (device globals: allocation-free) ----------------
__device__ float g_hseq[(size_t)T_STEPS * B_ROWS * HID];   // 256 MB
__device__ float g_xg[(size_t)T_STEPS * B_ROWS * NG];      // 1 GB
__device__ float g_hT[B_ROWS * HID];

// ---------------- helpers ----------------
__device__ __forceinline__ ull pk2(float lo, float hi){
    ull r; asm("mov.b64 %0,{%1,%2};" : "=l"(r) : "f"(lo), "f"(hi)); return r;
}
__device__ __forceinline__ ull ffma2(ull a, ull b, ull c){
    ull d; asm("fma.rn.f32x2 %0,%1,%2,%3;" : "=l"(d) : "l"(a), "l"(b), "l"(c)); return d;
}
__device__ __forceinline__ float2 unpk(ull v){
    float2 r; asm("mov.b64 {%0,%1},%2;" : "=f"(r.x), "=f"(r.y) : "l"(v)); return r;
}
__device__ __forceinline__ float sigf(float x){
    return __fdividef(1.f, 1.f + __expf(-x));
}
__device__ __forceinline__ float tanhf_(float x){
    return 1.f - 2.f * __fdividef(1.f, __expf(2.f * x) + 1.f);
}

// ================= recurrent kernel (R12, frozen: KREGP=44) =================
// 128 CTAs x 256 threads. CTA b owns batch rows 2b, 2b+1.
// Thread tid owns gate rows j0=tid (i|f) and j1=tid+256 (g|o).
// Whh cols [0,88) in regs (44 ull/row = 176 regs), cols [88,128) in SMEM.
constexpr int KREGP = 44;
constexpr int KSM4  = 10;
constexpr int REC_SMEM_BASE = (KSM4*NG*4 + 2*HID + 2*NG) * 4;          // 86528
constexpr int REC_SMEM0     = REC_SMEM_BASE + 2*T_STEPS*4;             // 102912

template<int MODE>   // 0: layer0 (x folded, writes hseq) 1: mid 2: last (writes hT)
__global__ void __launch_bounds__(256, 1)
lstm_rec(const float* __restrict__ xin,
         const float* __restrict__ wih,
         const float* __restrict__ bih,
         const float* __restrict__ bhh,
         const float* __restrict__ Whh)
{
    extern __shared__ float sm[];
    float4* ws = (float4*)sm;             // [KSM4][NG] weight tail
    float*  sh = sm + KSM4*NG*4;          // [2][HID] hidden state
    float*  sg = sh + 2*HID;              // [2][NG]  activated gates
    float*  sx = sg + 2*NG;               // MODE0: [2][T] input cache

    const int tid = threadIdx.x;
    const int j0 = tid, j1 = tid + 256;
    const int r0 = blockIdx.x * 2;

    ull w0[KREGP], w1[KREGP];
    {
        const float* p0 = Whh + (size_t)j0 * HID;
        const float* p1 = Whh + (size_t)j1 * HID;
        #pragma unroll
        for (int p = 0; p < KREGP; p++){
            w0[p] = *(const ull*)(p0 + 2*p);
            w1[p] = *(const ull*)(p1 + 2*p);
        }
        #pragma unroll
        for (int q = 0; q < KSM4; q++){
            ws[q*NG + j0] = *(const float4*)(p0 + 2*KREGP + 4*q);
            ws[q*NG + j1] = *(const float4*)(p1 + 2*KREGP + 4*q);
        }
    }
    float wi0 = 0.f, wi1 = 0.f, bb0 = 0.f, bb1 = 0.f;
    if (MODE == 0){
        wi0 = wih[j0]; wi1 = wih[j1];
        bb0 = bih[j0] + bhh[j0]; bb1 = bih[j1] + bhh[j1];
        for (int i = tid; i < 2*T_STEPS; i += 256){
            int row = i >> 11, t = i & (T_STEPS-1);
            sx[i] = xin[(size_t)(r0 + row) * T_STEPS + t];
        }
    }
    if (tid < HID){ sh[tid] = 0.f; sh[HID + tid] = 0.f; }
    float c0 = 0.f, c1 = 0.f;
    __syncthreads();

    float nx00, nx01, nx10, nx11;
    if (MODE != 0){
        const float* xg = g_xg + (size_t)r0 * NG;
        nx00 = __ldcs(xg + j0);      nx10 = __ldcs(xg + j1);
        nx01 = __ldcs(xg + NG + j0); nx11 = __ldcs(xg + NG + j1);
    }

    #pragma unroll 1
    for (int t = 0; t < T_STEPS; t++){
        float in00, in01, in10, in11;
        if (MODE == 0){
            float xv0 = sx[t], xv1 = sx[T_STEPS + t];
            in00 = fmaf(xv0, wi0, bb0); in01 = fmaf(xv1, wi0, bb0);
            in10 = fmaf(xv0, wi1, bb1); in11 = fmaf(xv1, wi1, bb1);
        } else {
            in00 = nx00; in01 = nx01; in10 = nx10; in11 = nx11;
            int tn = (t + 1 < T_STEPS) ? t + 1 : t;
            const float* xgn = g_xg + ((size_t)tn * B_ROWS + r0) * NG;
            nx00 = __ldcs(xgn + j0);      nx10 = __ldcs(xgn + j1);
            nx01 = __ldcs(xgn + NG + j0); nx11 = __ldcs(xgn + NG + j1);
        }
        ull a00 = pk2(in00, 0.f), a01 = pk2(in01, 0.f);
        ull a10 = pk2(in10, 0.f), a11 = pk2(in11, 0.f);

        const ulonglong2* h0 = (const ulonglong2*)sh;
        const ulonglong2* h1 = (const ulonglong2*)(sh + HID);
        #pragma unroll
        for (int p = 0; p < KREGP/2; p++){
            ulonglong2 hp0 = h0[p], hp1 = h1[p];
            a00 = ffma2(w0[2*p],   hp0.x, a00);
            a00 = ffma2(w0[2*p+1], hp0.y, a00);
            a01 = ffma2(w0[2*p],   hp1.x, a01);
            a01 = ffma2(w0[2*p+1], hp1.y, a01);
            a10 = ffma2(w1[2*p],   hp0.x, a10);
            a10 = ffma2(w1[2*p+1], hp0.y, a10);
            a11 = ffma2(w1[2*p],   hp1.x, a11);
            a11 = ffma2(w1[2*p+1], hp1.y, a11);
        }
        #pragma unroll
        for (int q = 0; q < KSM4; q++){
            float4 v0 = ws[q*NG + j0];
            float4 v1 = ws[q*NG + j1];
            ulonglong2 hq0 = h0[KREGP/2 + q];
            ulonglong2 hq1 = h1[KREGP/2 + q];
            ull w0a = pk2(v0.x, v0.y), w0b = pk2(v0.z, v0.w);
            ull w1a = pk2(v1.x, v1.y), w1b = pk2(v1.z, v1.w);
            a00 = ffma2(w0a, hq0.x, a00); a00 = ffma2(w0b, hq0.y, a00);
            a01 = ffma2(w0a, hq1.x, a01); a01 = ffma2(w0b, hq1.y, a01);
            a10 = ffma2(w1a, hq0.x, a10); a10 = ffma2(w1b, hq0.y, a10);
            a11 = ffma2(w1a, hq1.x, a11); a11 = ffma2(w1b, hq1.y, a11);
        }
        float2 f00 = unpk(a00), f01 = unpk(a01), f10 = unpk(a10), f11 = unpk(a11);
        float g00 = f00.x + f00.y, g01 = f01.x + f01.y;
        float g10 = f10.x + f10.y, g11 = f11.x + f11.y;
        g00 = sigf(g00); g01 = sigf(g01);
        if (tid < 128){ g10 = tanhf_(g10); g11 = tanhf_(g11); }
        else          { g10 = sigf(g10);   g11 = sigf(g11);  }
        sg[j0]      = g00; sg[j1]      = g10;
        sg[NG + j0] = g01; sg[NG + j1] = g11;
        __syncthreads();
        {
            int row = tid >> 7, u = tid & 127;
            float* cc = (tid < 128) ? &c0 : &c1;
            const float* sgr = sg + row * NG;
            float iv = sgr[u], fv = sgr[HID+u], gv = sgr[2*HID+u], ov = sgr[3*HID+u];
            *cc = fmaf(fv, *cc, iv * gv);
            float hv = ov * tanhf_(*cc);
            sh[row * HID + u] = hv;
            if (MODE != 2){
                g_hseq[((size_t)t * B_ROWS + r0 + row) * HID + u] = hv;
            } else if (t == T_STEPS - 1){
                g_hT[(size_t)(r0 + row) * HID + u] = hv;
            }
        }
        __syncthreads();
    }
}

// ================= input-projection GEMM v5: 512 threads, 128x128 tiles =======
// C(M=524288,512) = hseq(M,128) @ W^T + bias. Persistent grid (37,4), 1 CTA/SM,
// 512 threads -> 4 warps/SMSP (latency hiding). v3 smem layout:
// B resident [k4][n] float4 (pad 129); A natural [m][k], double-buffered cp.async.
// Per-thread tile 4x8; B operands staged in two half-groups (reg cap 128).
constexpr int M_TILES   = (T_STEPS * B_ROWS) / 128;     // 4096
constexpr int GRID_X    = 37;
constexpr int A_TILE_F  = 128 * 128;                    // 16384 floats (64KB)
constexpr int BQ_F4     = 32 * 129;
constexpr int GEMM_SMEM = (2 * A_TILE_F) * 4 + BQ_F4 * 16;   // 197120 B

__global__ void __launch_bounds__(512, 1)
gemm_xg(const float* __restrict__ W,
        const float* __restrict__ ba,
        const float* __restrict__ bb)
{
    extern __shared__ float sm[];
    float*  As = sm;                             // [2][128][128]
    float4* Bq = (float4*)(sm + 2 * A_TILE_F);   // [32][129]

    const int tid = threadIdx.x;
    const int tx = tid & 15, ty = tid >> 4;      // ty 0..31 -> 4 rows each
    const int n0 = blockIdx.y * 128;

    #pragma unroll
    for (int i = 0; i < 8; i++){
        int idx = tid + i * 512;                  // over [128 n][32 k4]
        int n = idx >> 5, k4 = idx & 31;
        Bq[k4 * 129 + n] = *(const float4*)&W[(size_t)(n0 + n) * HID + 4 * k4];
    }

    float bias[8];
    #pragma unroll
    for (int c = 0; c < 8; c++){
        int n = n0 + tx + 16*c;
        bias[c] = __ldg(ba + n) + __ldg(bb + n);
    }

    uint sA = (uint)__cvta_generic_to_shared(As);
    auto issue = [&](int mt, int buf){
        const float* src = g_hseq + (size_t)mt * A_TILE_F;
        uint dst = sA + buf * (A_TILE_F * 4);
        #pragma unroll
        for (int i = 0; i < 8; i++){
            int idx = tid + i * 512;              // 4096 float4 chunks
            asm volatile("cp.async.cg.shared.global [%0], [%1], 16;\n"
                         :: "r"(dst + idx * 16), "l"(src + idx * 4));
        }
        asm volatile("cp.async.commit_group;\n" ::: "memory");
    };

    int mt = blockIdx.x;
    if (mt < M_TILES) issue(mt, 0);
    int buf = 0;

    #pragma unroll 1
    for (; mt < M_TILES; mt += GRID_X){
        int nxt = mt + GRID_X;
        if (nxt < M_TILES) issue(nxt, buf ^ 1);
        if (nxt < M_TILES) asm volatile("cp.async.wait_group 1;\n" ::: "memory");
        else               asm volatile("cp.async.wait_group 0;\n" ::: "memory");
        __syncthreads();

        const float* Ab = As + buf * A_TILE_F;
        ull acc[4][8];
        #pragma unroll
        for (int r = 0; r < 4; r++)
            #pragma unroll
            for (int c = 0; c < 8; c++) acc[r][c] = 0ULL;

        #pragma unroll 2
        for (int kp2 = 0; kp2 < 32; kp2++){
            ulonglong2 a2[4];
            #pragma unroll
            for (int r = 0; r < 4; r++)
                a2[r] = *(const ulonglong2*)&Ab[(ty*4 + r) * 128 + 4*kp2];
            #pragma unroll
            for (int h = 0; h < 2; h++){
                ulonglong2 b2[4];
                #pragma unroll
                for (int c = 0; c < 4; c++)
                    b2[c] = ((const ulonglong2*)Bq)[kp2 * 129 + tx + 16*(h*4 + c)];
                #pragma unroll
                for (int r = 0; r < 4; r++)
                    #pragma unroll
                    for (int c = 0; c < 4; c++){
                        acc[r][h*4 + c] = ffma2(a2[r].x, b2[c].x, acc[r][h*4 + c]);
                        acc[r][h*4 + c] = ffma2(a2[r].y, b2[c].y, acc[r][h*4 + c]);
                    }
            }
        }

        #pragma unroll
        for (int c = 0; c < 8; c++){
            int n = tx + 16*c;
            #pragma unroll
            for (int r = 0; r < 4; r++){
                float2 v = unpk(acc[r][c]);
                g_xg[((size_t)mt * 128 + ty*4 + r) * NG + n0 + n] = v.x + v.y + bias[c];
            }
        }
        __syncthreads();
        buf ^= 1;
    }
}

// ================= FC head =================
__global__ void head_kernel(const float* __restrict__ w1, const float* __restrict__ b1,
                            const float* __restrict__ w2, const float* __restrict__ b2,
                            float* __restrict__ out)
{
    __shared__ float z[64];
    int b = blockIdx.x, u = threadIdx.x;
    const float* h = g_hT + (size_t)b * HID;
    float acc = b1[u];
    const float* w = w1 + (size_t)u * HID;
    #pragma unroll 4
    for (int k = 0; k < HID; k++) acc = fmaf(w[k], h[k], acc);
    z[u] = fmaxf(acc, 0.f);
    __syncthreads();
    if (u < 5){
        float a2 = b2[u];
        const float* ww = w2 + u * 64;
        #pragma unroll 4
        for (int k = 0; k < 64; k++) a2 = fmaf(ww[k], z[k], a2);
        out[b * 5 + u] = a2;
    }
}

// ================= launch =================
extern "C" void kernel_launch(void* const* d_in, const int* in_sizes, int n_in,
                              void* d_out, int out_size)
{
    const float* x    = (const float*)d_in[0];
    const float* Wih0 = (const float*)d_in[1];
    const float* Whh0 = (const float*)d_in[2];
    const float* bih0 = (const float*)d_in[3];
    const float* bhh0 = (const float*)d_in[4];
    const float* Wih1 = (const float*)d_in[5];
    const float* Whh1 = (const float*)d_in[6];
    const float* bih1 = (const float*)d_in[7];
    const float* bhh1 = (const float*)d_in[8];
    const float* Wih2 = (const float*)d_in[9];
    const float* Whh2 = (const float*)d_in[10];
    const float* bih2 = (const float*)d_in[11];
    const float* bhh2 = (const float*)d_in[12];
    const float* fc1w = (const float*)d_in[13];
    const float* fc1b = (const float*)d_in[14];
    const float* fc2w = (const float*)d_in[15];
    const float* fc2b = (const float*)d_in[16];
    float* out = (float*)d_out;

    cudaFuncSetAttribute(lstm_rec<0>, cudaFuncAttributeMaxDynamicSharedMemorySize, REC_SMEM0);
    cudaFuncSetAttribute(lstm_rec<1>, cudaFuncAttributeMaxDynamicSharedMemorySize, REC_SMEM_BASE);
    cudaFuncSetAttribute(lstm_rec<2>, cudaFuncAttributeMaxDynamicSharedMemorySize, REC_SMEM_BASE);
    cudaFuncSetAttribute(gemm_xg,     cudaFuncAttributeMaxDynamicSharedMemorySize, GEMM_SMEM);

    lstm_rec<0><<<128, 256, REC_SMEM0>>>(x, Wih0, bih0, bhh0, Whh0);
    gemm_xg<<<dim3(GRID_X, 4), 512, GEMM_SMEM>>>(Wih1, bih1, bhh1);
    lstm_rec<1><<<128, 256, REC_SMEM_BASE>>>(nullptr, nullptr, nullptr, nullptr, Whh1);
    gemm_xg<<<dim3(GRID_X, 4), 512, GEMM_SMEM>>>(Wih2, bih2, bhh2);
    lstm_rec<2><<<128, 256, REC_SMEM_BASE>>>(nullptr, nullptr, nullptr, nullptr, Whh2);
    head_kernel<<<B_ROWS, 64>>>(fc1w, fc1b, fc2w, fc2b, out);
}

// round 15
// speedup vs baseline: 1.2176x; 1.0091x over previous
#include <cuda_runtime.h>

typedef unsigned long long ull;
typedef unsigned int uint;

#define T_STEPS 2048
#define B_ROWS  256
#define HID     128
#define NG      512

// ---------------- scratch (device globals: allocation-free) ----------------
__device__ float g_hseq[(size_t)T_STEPS * B_ROWS * HID];   // 256 MB
__device__ float g_xg[(size_t)T_STEPS * B_ROWS * NG];      // 1 GB
__device__ float g_hT[B_ROWS * HID];

// ---------------- helpers ----------------
__device__ __forceinline__ ull pk2(float lo, float hi){
    ull r; asm("mov.b64 %0,{%1,%2};" : "=l"(r) : "f"(lo), "f"(hi)); return r;
}
__device__ __forceinline__ ull ffma2(ull a, ull b, ull c){
    ull d; asm("fma.rn.f32x2 %0,%1,%2,%3;" : "=l"(d) : "l"(a), "l"(b), "l"(c)); return d;
}
__device__ __forceinline__ float2 unpk(ull v){
    float2 r; asm("mov.b64 {%0,%1},%2;" : "=f"(r.x), "=f"(r.y) : "l"(v)); return r;
}
__device__ __forceinline__ float sigf(float x){
    return __fdividef(1.f, 1.f + __expf(-x));
}
__device__ __forceinline__ float tanhf_(float x){
    return 1.f - 2.f * __fdividef(1.f, __expf(2.f * x) + 1.f);
}

// ================= recurrent kernel (R12, frozen: KREGP=44) =================
// 128 CTAs x 256 threads. CTA b owns batch rows 2b, 2b+1.
// Thread tid owns gate rows j0=tid (i|f) and j1=tid+256 (g|o).
// Whh cols [0,88) in regs (44 ull/row = 176 regs), cols [88,128) in SMEM.
constexpr int KREGP = 44;
constexpr int KSM4  = 10;
constexpr int REC_SMEM_BASE = (KSM4*NG*4 + 2*HID + 2*NG) * 4;          // 86528
constexpr int REC_SMEM0     = REC_SMEM_BASE + 2*T_STEPS*4;             // 102912

template<int MODE>   // 0: layer0 (x folded, writes hseq) 1: mid 2: last (writes hT)
__global__ void __launch_bounds__(256, 1)
lstm_rec(const float* __restrict__ xin,
         const float* __restrict__ wih,
         const float* __restrict__ bih,
         const float* __restrict__ bhh,
         const float* __restrict__ Whh)
{
    extern __shared__ float sm[];
    float4* ws = (float4*)sm;             // [KSM4][NG] weight tail
    float*  sh = sm + KSM4*NG*4;          // [2][HID] hidden state
    float*  sg = sh + 2*HID;              // [2][NG]  activated gates
    float*  sx = sg + 2*NG;               // MODE0: [2][T] input cache

    const int tid = threadIdx.x;
    const int j0 = tid, j1 = tid + 256;
    const int r0 = blockIdx.x * 2;

    ull w0[KREGP], w1[KREGP];
    {
        const float* p0 = Whh + (size_t)j0 * HID;
        const float* p1 = Whh + (size_t)j1 * HID;
        #pragma unroll
        for (int p = 0; p < KREGP; p++){
            w0[p] = *(const ull*)(p0 + 2*p);
            w1[p] = *(const ull*)(p1 + 2*p);
        }
        #pragma unroll
        for (int q = 0; q < KSM4; q++){
            ws[q*NG + j0] = *(const float4*)(p0 + 2*KREGP + 4*q);
            ws[q*NG + j1] = *(const float4*)(p1 + 2*KREGP + 4*q);
        }
    }
    float wi0 = 0.f, wi1 = 0.f, bb0 = 0.f, bb1 = 0.f;
    if (MODE == 0){
        wi0 = wih[j0]; wi1 = wih[j1];
        bb0 = bih[j0] + bhh[j0]; bb1 = bih[j1] + bhh[j1];
        for (int i = tid; i < 2*T_STEPS; i += 256){
            int row = i >> 11, t = i & (T_STEPS-1);
            sx[i] = xin[(size_t)(r0 + row) * T_STEPS + t];
        }
    }
    if (tid < HID){ sh[tid] = 0.f; sh[HID + tid] = 0.f; }
    float c0 = 0.f, c1 = 0.f;
    __syncthreads();

    float nx00, nx01, nx10, nx11;
    if (MODE != 0){
        const float* xg = g_xg + (size_t)r0 * NG;
        nx00 = __ldcs(xg + j0);      nx10 = __ldcs(xg + j1);
        nx01 = __ldcs(xg + NG + j0); nx11 = __ldcs(xg + NG + j1);
    }

    #pragma unroll 1
    for (int t = 0; t < T_STEPS; t++){
        float in00, in01, in10, in11;
        if (MODE == 0){
            float xv0 = sx[t], xv1 = sx[T_STEPS + t];
            in00 = fmaf(xv0, wi0, bb0); in01 = fmaf(xv1, wi0, bb0);
            in10 = fmaf(xv0, wi1, bb1); in11 = fmaf(xv1, wi1, bb1);
        } else {
            in00 = nx00; in01 = nx01; in10 = nx10; in11 = nx11;
            int tn = (t + 1 < T_STEPS) ? t + 1 : t;
            const float* xgn = g_xg + ((size_t)tn * B_ROWS + r0) * NG;
            nx00 = __ldcs(xgn + j0);      nx10 = __ldcs(xgn + j1);
            nx01 = __ldcs(xgn + NG + j0); nx11 = __ldcs(xgn + NG + j1);
        }
        ull a00 = pk2(in00, 0.f), a01 = pk2(in01, 0.f);
        ull a10 = pk2(in10, 0.f), a11 = pk2(in11, 0.f);

        const ulonglong2* h0 = (const ulonglong2*)sh;
        const ulonglong2* h1 = (const ulonglong2*)(sh + HID);
        #pragma unroll
        for (int p = 0; p < KREGP/2; p++){
            ulonglong2 hp0 = h0[p], hp1 = h1[p];
            a00 = ffma2(w0[2*p],   hp0.x, a00);
            a00 = ffma2(w0[2*p+1], hp0.y, a00);
            a01 = ffma2(w0[2*p],   hp1.x, a01);
            a01 = ffma2(w0[2*p+1], hp1.y, a01);
            a10 = ffma2(w1[2*p],   hp0.x, a10);
            a10 = ffma2(w1[2*p+1], hp0.y, a10);
            a11 = ffma2(w1[2*p],   hp1.x, a11);
            a11 = ffma2(w1[2*p+1], hp1.y, a11);
        }
        #pragma unroll
        for (int q = 0; q < KSM4; q++){
            float4 v0 = ws[q*NG + j0];
            float4 v1 = ws[q*NG + j1];
            ulonglong2 hq0 = h0[KREGP/2 + q];
            ulonglong2 hq1 = h1[KREGP/2 + q];
            ull w0a = pk2(v0.x, v0.y), w0b = pk2(v0.z, v0.w);
            ull w1a = pk2(v1.x, v1.y), w1b = pk2(v1.z, v1.w);
            a00 = ffma2(w0a, hq0.x, a00); a00 = ffma2(w0b, hq0.y, a00);
            a01 = ffma2(w0a, hq1.x, a01); a01 = ffma2(w0b, hq1.y, a01);
            a10 = ffma2(w1a, hq0.x, a10); a10 = ffma2(w1b, hq0.y, a10);
            a11 = ffma2(w1a, hq1.x, a11); a11 = ffma2(w1b, hq1.y, a11);
        }
        float2 f00 = unpk(a00), f01 = unpk(a01), f10 = unpk(a10), f11 = unpk(a11);
        float g00 = f00.x + f00.y, g01 = f01.x + f01.y;
        float g10 = f10.x + f10.y, g11 = f11.x + f11.y;
        g00 = sigf(g00); g01 = sigf(g01);
        if (tid < 128){ g10 = tanhf_(g10); g11 = tanhf_(g11); }
        else          { g10 = sigf(g10);   g11 = sigf(g11);  }
        sg[j0]      = g00; sg[j1]      = g10;
        sg[NG + j0] = g01; sg[NG + j1] = g11;
        __syncthreads();
        {
            int row = tid >> 7, u = tid & 127;
            float* cc = (tid < 128) ? &c0 : &c1;
            const float* sgr = sg + row * NG;
            float iv = sgr[u], fv = sgr[HID+u], gv = sgr[2*HID+u], ov = sgr[3*HID+u];
            *cc = fmaf(fv, *cc, iv * gv);
            float hv = ov * tanhf_(*cc);
            sh[row * HID + u] = hv;
            if (MODE != 2){
                g_hseq[((size_t)t * B_ROWS + r0 + row) * HID + u] = hv;
            } else if (t == T_STEPS - 1){
                g_hT[(size_t)(r0 + row) * HID + u] = hv;
            }
        }
        __syncthreads();
    }
}

// ================= input-projection GEMM v6: v3 + kp2 unroll 2 ===============
// C(M=524288,512) = hseq(M,128) @ W^T + bias. Persistent grid (37,4).
// B resident in smem as [k4][n] float4 (pad 129). A natural [m][k],
// double-buffered cp.async. Inner loop LDS.128 only; unroll 2 lets ptxas
// prefetch kp2+1 operands under kp2's FFMA2 stream (hide 29-cyc LDS latency).
constexpr int M_TILES   = (T_STEPS * B_ROWS) / 128;     // 4096
constexpr int GRID_X    = 37;
constexpr int A_TILE_F  = 128 * 128;
constexpr int BQ_F4     = 32 * 129;
constexpr int GEMM_SMEM = (2 * A_TILE_F) * 4 + BQ_F4 * 16;   // 197120 B

__global__ void __launch_bounds__(256, 1)
gemm_xg(const float* __restrict__ W,
        const float* __restrict__ ba,
        const float* __restrict__ bb)
{
    extern __shared__ float sm[];
    float*  As = sm;                             // [2][128][128]
    float4* Bq = (float4*)(sm + 2 * A_TILE_F);   // [32][129]

    const int tid = threadIdx.x;
    const int tx = tid & 15, ty = tid >> 4;
    const int n0 = blockIdx.y * 128;

    #pragma unroll
    for (int i = 0; i < 16; i++){
        int idx = tid + i * 256;                  // over [128 n][32 k4]
        int n = idx >> 5, k4 = idx & 31;
        Bq[k4 * 129 + n] = *(const float4*)&W[(size_t)(n0 + n) * HID + 4 * k4];
    }

    float bias[8];
    #pragma unroll
    for (int c = 0; c < 8; c++){
        int n = n0 + tx + 16*c;
        bias[c] = __ldg(ba + n) + __ldg(bb + n);
    }

    uint sA = (uint)__cvta_generic_to_shared(As);
    auto issue = [&](int mt, int buf){
        const float* src = g_hseq + (size_t)mt * A_TILE_F;
        uint dst = sA + buf * (A_TILE_F * 4);
        #pragma unroll
        for (int i = 0; i < 16; i++){
            int idx = tid + i * 256;
            asm volatile("cp.async.cg.shared.global [%0], [%1], 16;\n"
                         :: "r"(dst + idx * 16), "l"(src + idx * 4));
        }
        asm volatile("cp.async.commit_group;\n" ::: "memory");
    };

    int mt = blockIdx.x;
    if (mt < M_TILES) issue(mt, 0);
    int buf = 0;

    #pragma unroll 1
    for (; mt < M_TILES; mt += GRID_X){
        int nxt = mt + GRID_X;
        if (nxt < M_TILES) issue(nxt, buf ^ 1);
        if (nxt < M_TILES) asm volatile("cp.async.wait_group 1;\n" ::: "memory");
        else               asm volatile("cp.async.wait_group 0;\n" ::: "memory");
        __syncthreads();

        const float* Ab = As + buf * A_TILE_F;
        ull acc[8][8];
        #pragma unroll
        for (int r = 0; r < 8; r++)
            #pragma unroll
            for (int c = 0; c < 8; c++) acc[r][c] = 0ULL;

        #pragma unroll 2
        for (int kp2 = 0; kp2 < 32; kp2++){
            ulonglong2 a2[8], b2[8];
            #pragma unroll
            for (int r = 0; r < 8; r++)
                a2[r] = *(const ulonglong2*)&Ab[(ty*8 + r) * 128 + 4*kp2];
            #pragma unroll
            for (int c = 0; c < 8; c++)
                b2[c] = ((const ulonglong2*)Bq)[kp2 * 129 + tx + 16*c];
            #pragma unroll
            for (int r = 0; r < 8; r++)
                #pragma unroll
                for (int c = 0; c < 8; c++){
                    acc[r][c] = ffma2(a2[r].x, b2[c].x, acc[r][c]);
                    acc[r][c] = ffma2(a2[r].y, b2[c].y, acc[r][c]);
                }
        }

        #pragma unroll
        for (int c = 0; c < 8; c++){
            int n = tx + 16*c;
            #pragma unroll
            for (int r = 0; r < 8; r++){
                float2 v = unpk(acc[r][c]);
                g_xg[((size_t)mt * 128 + ty*8 + r) * NG + n0 + n] = v.x + v.y + bias[c];
            }
        }
        __syncthreads();
        buf ^= 1;
    }
}

// ================= FC head =================
__global__ void head_kernel(const float* __restrict__ w1, const float* __restrict__ b1,
                            const float* __restrict__ w2, const float* __restrict__ b2,
                            float* __restrict__ out)
{
    __shared__ float z[64];
    int b = blockIdx.x, u = threadIdx.x;
    const float* h = g_hT + (size_t)b * HID;
    float acc = b1[u];
    const float* w = w1 + (size_t)u * HID;
    #pragma unroll 4
    for (int k = 0; k < HID; k++) acc = fmaf(w[k], h[k], acc);
    z[u] = fmaxf(acc, 0.f);
    __syncthreads();
    if (u < 5){
        float a2 = b2[u];
        const float* ww = w2 + u * 64;
        #pragma unroll 4
        for (int k = 0; k < 64; k++) a2 = fmaf(ww[k], z[k], a2);
        out[b * 5 + u] = a2;
    }
}

// ================= launch =================
extern "C" void kernel_launch(void* const* d_in, const int* in_sizes, int n_in,
                              void* d_out, int out_size)
{
    const float* x    = (const float*)d_in[0];
    const float* Wih0 = (const float*)d_in[1];
    const float* Whh0 = (const float*)d_in[2];
    const float* bih0 = (const float*)d_in[3];
    const float* bhh0 = (const float*)d_in[4];
    const float* Wih1 = (const float*)d_in[5];
    const float* Whh1 = (const float*)d_in[6];
    const float* bih1 = (const float*)d_in[7];
    const float* bhh1 = (const float*)d_in[8];
    const float* Wih2 = (const float*)d_in[9];
    const float* Whh2 = (const float*)d_in[10];
    const float* bih2 = (const float*)d_in[11];
    const float* bhh2 = (const float*)d_in[12];
    const float* fc1w = (const float*)d_in[13];
    const float* fc1b = (const float*)d_in[14];
    const float* fc2w = (const float*)d_in[15];
    const float* fc2b = (const float*)d_in[16];
    float* out = (float*)d_out;

    cudaFuncSetAttribute(lstm_rec<0>, cudaFuncAttributeMaxDynamicSharedMemorySize, REC_SMEM0);
    cudaFuncSetAttribute(lstm_rec<1>, cudaFuncAttributeMaxDynamicSharedMemorySize, REC_SMEM_BASE);
    cudaFuncSetAttribute(lstm_rec<2>, cudaFuncAttributeMaxDynamicSharedMemorySize, REC_SMEM_BASE);
    cudaFuncSetAttribute(gemm_xg,     cudaFuncAttributeMaxDynamicSharedMemorySize, GEMM_SMEM);

    lstm_rec<0><<<128, 256, REC_SMEM0>>>(x, Wih0, bih0, bhh0, Whh0);
    gemm_xg<<<dim3(GRID_X, 4), 256, GEMM_SMEM>>>(Wih1, bih1, bhh1);
    lstm_rec<1><<<128, 256, REC_SMEM_BASE>>>(nullptr, nullptr, nullptr, nullptr, Whh1);
    gemm_xg<<<dim3(GRID_X, 4), 256, GEMM_SMEM>>>(Wih2, bih2, bhh2);
    lstm_rec<2><<<128, 256, REC_SMEM_BASE>>>(nullptr, nullptr, nullptr, nullptr, Whh2);
    head_kernel<<<B_ROWS, 64>>>(fc1w, fc1b, fc2w, fc2b, out);
}

// round 16
// speedup vs baseline: 1.2526x; 1.0287x over previous
#include <cuda_runtime.h>

typedef unsigned long long ull;
typedef unsigned int uint;

#define T_STEPS 2048
#define B_ROWS  256
#define HID     128
#define NG      512

// ---------------- scratch (device globals: allocation-free) ----------------
__device__ float g_hseq[(size_t)T_STEPS * B_ROWS * HID];   // 256 MB
__device__ float g_xg[(size_t)T_STEPS * B_ROWS * NG];      // 1 GB
__device__ float g_hT[B_ROWS * HID];

// ---------------- helpers ----------------
__device__ __forceinline__ ull pk2(float lo, float hi){
    ull r; asm("mov.b64 %0,{%1,%2};" : "=l"(r) : "f"(lo), "f"(hi)); return r;
}
__device__ __forceinline__ ull ffma2(ull a, ull b, ull c){
    ull d; asm("fma.rn.f32x2 %0,%1,%2,%3;" : "=l"(d) : "l"(a), "l"(b), "l"(c)); return d;
}
__device__ __forceinline__ float2 unpk(ull v){
    float2 r; asm("mov.b64 {%0,%1},%2;" : "=f"(r.x), "=f"(r.y) : "l"(v)); return r;
}
__device__ __forceinline__ float sigf(float x){
    return __fdividef(1.f, 1.f + __expf(-x));
}
__device__ __forceinline__ float tanhf_(float x){
    return 1.f - 2.f * __fdividef(1.f, __expf(2.f * x) + 1.f);
}

// ================= recurrent kernel (R12 source, frozen: KREGP=44) ===========
// 128 CTAs x 256 threads. CTA b owns batch rows 2b, 2b+1.
// Thread tid owns gate rows j0=tid (i|f) and j1=tid+256 (g|o).
// Whh cols [0,88) in regs (44 ull/row = 176 regs), cols [88,128) in SMEM.
constexpr int KREGP = 44;
constexpr int KSM4  = 10;
constexpr int REC_SMEM_BASE = (KSM4*NG*4 + 2*HID + 2*NG) * 4;          // 86528
constexpr int REC_SMEM0     = REC_SMEM_BASE + 2*T_STEPS*4;             // 102912

template<int MODE>   // 0: layer0 (x folded, writes hseq) 1: mid 2: last (writes hT)
__global__ void __launch_bounds__(256, 1)
lstm_rec(const float* __restrict__ xin,
         const float* __restrict__ wih,
         const float* __restrict__ bih,
         const float* __restrict__ bhh,
         const float* __restrict__ Whh)
{
    extern __shared__ float sm[];
    float4* ws = (float4*)sm;             // [KSM4][NG] weight tail
    float*  sh = sm + KSM4*NG*4;          // [2][HID] hidden state
    float*  sg = sh + 2*HID;              // [2][NG]  activated gates
    float*  sx = sg + 2*NG;               // MODE0: [2][T] input cache

    const int tid = threadIdx.x;
    const int j0 = tid, j1 = tid + 256;
    const int r0 = blockIdx.x * 2;

    ull w0[KREGP], w1[KREGP];
    {
        const float* p0 = Whh + (size_t)j0 * HID;
        const float* p1 = Whh + (size_t)j1 * HID;
        #pragma unroll
        for (int p = 0; p < KREGP; p++){
            w0[p] = *(const ull*)(p0 + 2*p);
            w1[p] = *(const ull*)(p1 + 2*p);
        }
        #pragma unroll
        for (int q = 0; q < KSM4; q++){
            ws[q*NG + j0] = *(const float4*)(p0 + 2*KREGP + 4*q);
            ws[q*NG + j1] = *(const float4*)(p1 + 2*KREGP + 4*q);
        }
    }
    float wi0 = 0.f, wi1 = 0.f, bb0 = 0.f, bb1 = 0.f;
    if (MODE == 0){
        wi0 = wih[j0]; wi1 = wih[j1];
        bb0 = bih[j0] + bhh[j0]; bb1 = bih[j1] + bhh[j1];
        for (int i = tid; i < 2*T_STEPS; i += 256){
            int row = i >> 11, t = i & (T_STEPS-1);
            sx[i] = xin[(size_t)(r0 + row) * T_STEPS + t];
        }
    }
    if (tid < HID){ sh[tid] = 0.f; sh[HID + tid] = 0.f; }
    float c0 = 0.f, c1 = 0.f;
    __syncthreads();

    float nx00, nx01, nx10, nx11;
    if (MODE != 0){
        const float* xg = g_xg + (size_t)r0 * NG;
        nx00 = __ldcs(xg + j0);      nx10 = __ldcs(xg + j1);
        nx01 = __ldcs(xg + NG + j0); nx11 = __ldcs(xg + NG + j1);
    }

    #pragma unroll 1
    for (int t = 0; t < T_STEPS; t++){
        float in00, in01, in10, in11;
        if (MODE == 0){
            float xv0 = sx[t], xv1 = sx[T_STEPS + t];
            in00 = fmaf(xv0, wi0, bb0); in01 = fmaf(xv1, wi0, bb0);
            in10 = fmaf(xv0, wi1, bb1); in11 = fmaf(xv1, wi1, bb1);
        } else {
            in00 = nx00; in01 = nx01; in10 = nx10; in11 = nx11;
            int tn = (t + 1 < T_STEPS) ? t + 1 : t;
            const float* xgn = g_xg + ((size_t)tn * B_ROWS + r0) * NG;
            nx00 = __ldcs(xgn + j0);      nx10 = __ldcs(xgn + j1);
            nx01 = __ldcs(xgn + NG + j0); nx11 = __ldcs(xgn + NG + j1);
        }
        ull a00 = pk2(in00, 0.f), a01 = pk2(in01, 0.f);
        ull a10 = pk2(in10, 0.f), a11 = pk2(in11, 0.f);

        const ulonglong2* h0 = (const ulonglong2*)sh;
        const ulonglong2* h1 = (const ulonglong2*)(sh + HID);
        #pragma unroll
        for (int p = 0; p < KREGP/2; p++){
            ulonglong2 hp0 = h0[p], hp1 = h1[p];
            a00 = ffma2(w0[2*p],   hp0.x, a00);
            a00 = ffma2(w0[2*p+1], hp0.y, a00);
            a01 = ffma2(w0[2*p],   hp1.x, a01);
            a01 = ffma2(w0[2*p+1], hp1.y, a01);
            a10 = ffma2(w1[2*p],   hp0.x, a10);
            a10 = ffma2(w1[2*p+1], hp0.y, a10);
            a11 = ffma2(w1[2*p],   hp1.x, a11);
            a11 = ffma2(w1[2*p+1], hp1.y, a11);
        }
        #pragma unroll
        for (int q = 0; q < KSM4; q++){
            float4 v0 = ws[q*NG + j0];
            float4 v1 = ws[q*NG + j1];
            ulonglong2 hq0 = h0[KREGP/2 + q];
            ulonglong2 hq1 = h1[KREGP/2 + q];
            ull w0a = pk2(v0.x, v0.y), w0b = pk2(v0.z, v0.w);
            ull w1a = pk2(v1.x, v1.y), w1b = pk2(v1.z, v1.w);
            a00 = ffma2(w0a, hq0.x, a00); a00 = ffma2(w0b, hq0.y, a00);
            a01 = ffma2(w0a, hq1.x, a01); a01 = ffma2(w0b, hq1.y, a01);
            a10 = ffma2(w1a, hq0.x, a10); a10 = ffma2(w1b, hq0.y, a10);
            a11 = ffma2(w1a, hq1.x, a11); a11 = ffma2(w1b, hq1.y, a11);
        }
        float2 f00 = unpk(a00), f01 = unpk(a01), f10 = unpk(a10), f11 = unpk(a11);
        float g00 = f00.x + f00.y, g01 = f01.x + f01.y;
        float g10 = f10.x + f10.y, g11 = f11.x + f11.y;
        g00 = sigf(g00); g01 = sigf(g01);
        if (tid < 128){ g10 = tanhf_(g10); g11 = tanhf_(g11); }
        else          { g10 = sigf(g10);   g11 = sigf(g11);  }
        sg[j0]      = g00; sg[j1]      = g10;
        sg[NG + j0] = g01; sg[NG + j1] = g11;
        __syncthreads();
        {
            int row = tid >> 7, u = tid & 127;
            float* cc = (tid < 128) ? &c0 : &c1;
            const float* sgr = sg + row * NG;
            float iv = sgr[u], fv = sgr[HID+u], gv = sgr[2*HID+u], ov = sgr[3*HID+u];
            *cc = fmaf(fv, *cc, iv * gv);
            float hv = ov * tanhf_(*cc);
            sh[row * HID + u] = hv;
            if (MODE != 2){
                g_hseq[((size_t)t * B_ROWS + r0 + row) * HID + u] = hv;
            } else if (t == T_STEPS - 1){
                g_hT[(size_t)(r0 + row) * HID + u] = hv;
            }
        }
        __syncthreads();
    }
}

// ================= input-projection GEMM v3 (R8 source, frozen) ==============
// C(M=524288,512) = hseq(M,128) @ W^T + bias. Persistent grid (37,4).
// B resident in smem as [k4][n] float4 (pad 129). A natural [m][k],
// double-buffered cp.async. Inner loop LDS.128 only, unroll 1. 198 regs.
constexpr int M_TILES   = (T_STEPS * B_ROWS) / 128;     // 4096
constexpr int GRID_X    = 37;
constexpr int A_TILE_F  = 128 * 128;
constexpr int BQ_F4     = 32 * 129;
constexpr int GEMM_SMEM = (2 * A_TILE_F) * 4 + BQ_F4 * 16;   // 197120 B

__global__ void __launch_bounds__(256, 1)
gemm_xg(const float* __restrict__ W,
        const float* __restrict__ ba,
        const float* __restrict__ bb)
{
    extern __shared__ float sm[];
    float*  As = sm;                             // [2][128][128]
    float4* Bq = (float4*)(sm + 2 * A_TILE_F);   // [32][129]

    const int tid = threadIdx.x;
    const int tx = tid & 15, ty = tid >> 4;
    const int n0 = blockIdx.y * 128;

    #pragma unroll
    for (int i = 0; i < 16; i++){
        int idx = tid + i * 256;                  // over [128 n][32 k4]
        int n = idx >> 5, k4 = idx & 31;
        Bq[k4 * 129 + n] = *(const float4*)&W[(size_t)(n0 + n) * HID + 4 * k4];
    }

    float bias[8];
    #pragma unroll
    for (int c = 0; c < 8; c++){
        int n = n0 + tx + 16*c;
        bias[c] = __ldg(ba + n) + __ldg(bb + n);
    }

    uint sA = (uint)__cvta_generic_to_shared(As);
    auto issue = [&](int mt, int buf){
        const float* src = g_hseq + (size_t)mt * A_TILE_F;
        uint dst = sA + buf * (A_TILE_F * 4);
        #pragma unroll
        for (int i = 0; i < 16; i++){
            int idx = tid + i * 256;
            asm volatile("cp.async.cg.shared.global [%0], [%1], 16;\n"
                         :: "r"(dst + idx * 16), "l"(src + idx * 4));
        }
        asm volatile("cp.async.commit_group;\n" ::: "memory");
    };

    int mt = blockIdx.x;
    if (mt < M_TILES) issue(mt, 0);
    int buf = 0;

    #pragma unroll 1
    for (; mt < M_TILES; mt += GRID_X){
        int nxt = mt + GRID_X;
        if (nxt < M_TILES) issue(nxt, buf ^ 1);
        if (nxt < M_TILES) asm volatile("cp.async.wait_group 1;\n" ::: "memory");
        else               asm volatile("cp.async.wait_group 0;\n" ::: "memory");
        __syncthreads();

        const float* Ab = As + buf * A_TILE_F;
        ull acc[8][8];
        #pragma unroll
        for (int r = 0; r < 8; r++)
            #pragma unroll
            for (int c = 0; c < 8; c++) acc[r][c] = 0ULL;

        #pragma unroll 1
        for (int kp2 = 0; kp2 < 32; kp2++){
            ulonglong2 a2[8], b2[8];
            #pragma unroll
            for (int r = 0; r < 8; r++)
                a2[r] = *(const ulonglong2*)&Ab[(ty*8 + r) * 128 + 4*kp2];
            #pragma unroll
            for (int c = 0; c < 8; c++)
                b2[c] = ((const ulonglong2*)Bq)[kp2 * 129 + tx + 16*c];
            #pragma unroll
            for (int r = 0; r < 8; r++)
                #pragma unroll
                for (int c = 0; c < 8; c++){
                    acc[r][c] = ffma2(a2[r].x, b2[c].x, acc[r][c]);
                    acc[r][c] = ffma2(a2[r].y, b2[c].y, acc[r][c]);
                }
        }

        #pragma unroll
        for (int c = 0; c < 8; c++){
            int n = tx + 16*c;
            #pragma unroll
            for (int r = 0; r < 8; r++){
                float2 v = unpk(acc[r][c]);
                g_xg[((size_t)mt * 128 + ty*8 + r) * NG + n0 + n] = v.x + v.y + bias[c];
            }
        }
        __syncthreads();
        buf ^= 1;
    }
}

// ================= FC head =================
__global__ void head_kernel(const float* __restrict__ w1, const float* __restrict__ b1,
                            const float* __restrict__ w2, const float* __restrict__ b2,
                            float* __restrict__ out)
{
    __shared__ float z[64];
    int b = blockIdx.x, u = threadIdx.x;
    const float* h = g_hT + (size_t)b * HID;
    float acc = b1[u];
    const float* w = w1 + (size_t)u * HID;
    #pragma unroll 4
    for (int k = 0; k < HID; k++) acc = fmaf(w[k], h[k], acc);
    z[u] = fmaxf(acc, 0.f);
    __syncthreads();
    if (u < 5){
        float a2 = b2[u];
        const float* ww = w2 + u * 64;
        #pragma unroll 4
        for (int k = 0; k < 64; k++) a2 = fmaf(ww[k], z[k], a2);
        out[b * 5 + u] = a2;
    }
}

// ================= launch =================
extern "C" void kernel_launch(void* const* d_in, const int* in_sizes, int n_in,
                              void* d_out, int out_size)
{
    const float* x    = (const float*)d_in[0];
    const float* Wih0 = (const float*)d_in[1];
    const float* Whh0 = (const float*)d_in[2];
    const float* bih0 = (const float*)d_in[3];
    const float* bhh0 = (const float*)d_in[4];
    const float* Wih1 = (const float*)d_in[5];
    const float* Whh1 = (const float*)d_in[6];
    const float* bih1 = (const float*)d_in[7];
    const float* bhh1 = (const float*)d_in[8];
    const float* Wih2 = (const float*)d_in[9];
    const float* Whh2 = (const float*)d_in[10];
    const float* bih2 = (const float*)d_in[11];
    const float* bhh2 = (const float*)d_in[12];
    const float* fc1w = (const float*)d_in[13];
    const float* fc1b = (const float*)d_in[14];
    const float* fc2w = (const float*)d_in[15];
    const float* fc2b = (const float*)d_in[16];
    float* out = (float*)d_out;

    cudaFuncSetAttribute(lstm_rec<0>, cudaFuncAttributeMaxDynamicSharedMemorySize, REC_SMEM0);
    cudaFuncSetAttribute(lstm_rec<1>, cudaFuncAttributeMaxDynamicSharedMemorySize, REC_SMEM_BASE);
    cudaFuncSetAttribute(lstm_rec<2>, cudaFuncAttributeMaxDynamicSharedMemorySize, REC_SMEM_BASE);
    cudaFuncSetAttribute(gemm_xg,     cudaFuncAttributeMaxDynamicSharedMemorySize, GEMM_SMEM);

    lstm_rec<0><<<128, 256, REC_SMEM0>>>(x, Wih0, bih0, bhh0, Whh0);
    gemm_xg<<<dim3(GRID_X, 4), 256, GEMM_SMEM>>>(Wih1, bih1, bhh1);
    lstm_rec<1><<<128, 256, REC_SMEM_BASE>>>(nullptr, nullptr, nullptr, nullptr, Whh1);
    gemm_xg<<<dim3(GRID_X, 4), 256, GEMM_SMEM>>>(Wih2, bih2, bhh2);
    lstm_rec<2><<<128, 256, REC_SMEM_BASE>>>(nullptr, nullptr, nullptr, nullptr, Whh2);
    head_kernel<<<B_ROWS, 64>>>(fc1w, fc1b, fc2w, fc2b, out);
}

// round 17
// speedup vs baseline: 1.2759x; 1.0186x over previous
#include <cuda_runtime.h>

typedef unsigned long long ull;
typedef unsigned int uint;

#define T_STEPS 2048
#define B_ROWS  256
#define HID     128
#define NG      512

// ---------------- scratch (device globals: allocation-free) ----------------
__device__ float g_hseq[(size_t)T_STEPS * B_ROWS * HID];   // 256 MB
__device__ float g_xg[(size_t)T_STEPS * B_ROWS * NG];      // 1 GB
__device__ float g_hT[B_ROWS * HID];

// ---------------- helpers ----------------
__device__ __forceinline__ ull pk2(float lo, float hi){
    ull r; asm("mov.b64 %0,{%1,%2};" : "=l"(r) : "f"(lo), "f"(hi)); return r;
}
__device__ __forceinline__ ull ffma2(ull a, ull b, ull c){
    ull d; asm("fma.rn.f32x2 %0,%1,%2,%3;" : "=l"(d) : "l"(a), "l"(b), "l"(c)); return d;
}
__device__ __forceinline__ float2 unpk(ull v){
    float2 r; asm("mov.b64 {%0,%1},%2;" : "=f"(r.x), "=f"(r.y) : "l"(v)); return r;
}
__device__ __forceinline__ float sigf(float x){
    return __fdividef(1.f, 1.f + __expf(-x));
}
__device__ __forceinline__ float tanhf_(float x){
    return 1.f - 2.f * __fdividef(1.f, __expf(2.f * x) + 1.f);
}

// ================= recurrent kernel (R12 structure, KREGP=48) ================
// 128 CTAs x 256 threads. CTA b owns batch rows 2b, 2b+1.
// Thread tid owns gate rows j0=tid (i|f) and j1=tid+256 (g|o).
// Whh cols [0,96) in regs (48 ull/row = 192 regs), cols [96,128) in SMEM.
constexpr int KREGP = 48;
constexpr int KSM4  = 8;
constexpr int REC_SMEM_BASE = (KSM4*NG*4 + 2*HID + 2*NG) * 4;          // 70656
constexpr int REC_SMEM0     = REC_SMEM_BASE + 2*T_STEPS*4;             // 87040

template<int MODE>   // 0: layer0 (x folded, writes hseq) 1: mid 2: last (writes hT)
__global__ void __launch_bounds__(256, 1)
lstm_rec(const float* __restrict__ xin,
         const float* __restrict__ wih,
         const float* __restrict__ bih,
         const float* __restrict__ bhh,
         const float* __restrict__ Whh)
{
    extern __shared__ float sm[];
    float4* ws = (float4*)sm;             // [KSM4][NG] weight tail
    float*  sh = sm + KSM4*NG*4;          // [2][HID] hidden state
    float*  sg = sh + 2*HID;              // [2][NG]  activated gates
    float*  sx = sg + 2*NG;               // MODE0: [2][T] input cache

    const int tid = threadIdx.x;
    const int j0 = tid, j1 = tid + 256;
    const int r0 = blockIdx.x * 2;

    ull w0[KREGP], w1[KREGP];
    {
        const float* p0 = Whh + (size_t)j0 * HID;
        const float* p1 = Whh + (size_t)j1 * HID;
        #pragma unroll
        for (int p = 0; p < KREGP; p++){
            w0[p] = *(const ull*)(p0 + 2*p);
            w1[p] = *(const ull*)(p1 + 2*p);
        }
        #pragma unroll
        for (int q = 0; q < KSM4; q++){
            ws[q*NG + j0] = *(const float4*)(p0 + 2*KREGP + 4*q);
            ws[q*NG + j1] = *(const float4*)(p1 + 2*KREGP + 4*q);
        }
    }
    float wi0 = 0.f, wi1 = 0.f, bb0 = 0.f, bb1 = 0.f;
    if (MODE == 0){
        wi0 = wih[j0]; wi1 = wih[j1];
        bb0 = bih[j0] + bhh[j0]; bb1 = bih[j1] + bhh[j1];
        for (int i = tid; i < 2*T_STEPS; i += 256){
            int row = i >> 11, t = i & (T_STEPS-1);
            sx[i] = xin[(size_t)(r0 + row) * T_STEPS + t];
        }
    }
    if (tid < HID){ sh[tid] = 0.f; sh[HID + tid] = 0.f; }
    float c0 = 0.f, c1 = 0.f;
    __syncthreads();

    float nx00, nx01, nx10, nx11;
    if (MODE != 0){
        const float* xg = g_xg + (size_t)r0 * NG;
        nx00 = __ldcs(xg + j0);      nx10 = __ldcs(xg + j1);
        nx01 = __ldcs(xg + NG + j0); nx11 = __ldcs(xg + NG + j1);
    }

    #pragma unroll 1
    for (int t = 0; t < T_STEPS; t++){
        float in00, in01, in10, in11;
        if (MODE == 0){
            float xv0 = sx[t], xv1 = sx[T_STEPS + t];
            in00 = fmaf(xv0, wi0, bb0); in01 = fmaf(xv1, wi0, bb0);
            in10 = fmaf(xv0, wi1, bb1); in11 = fmaf(xv1, wi1, bb1);
        } else {
            in00 = nx00; in01 = nx01; in10 = nx10; in11 = nx11;
            int tn = (t + 1 < T_STEPS) ? t + 1 : t;
            const float* xgn = g_xg + ((size_t)tn * B_ROWS + r0) * NG;
            nx00 = __ldcs(xgn + j0);      nx10 = __ldcs(xgn + j1);
            nx01 = __ldcs(xgn + NG + j0); nx11 = __ldcs(xgn + NG + j1);
        }
        ull a00 = pk2(in00, 0.f), a01 = pk2(in01, 0.f);
        ull a10 = pk2(in10, 0.f), a11 = pk2(in11, 0.f);

        const ulonglong2* h0 = (const ulonglong2*)sh;
        const ulonglong2* h1 = (const ulonglong2*)(sh + HID);
        #pragma unroll
        for (int p = 0; p < KREGP/2; p++){
            ulonglong2 hp0 = h0[p], hp1 = h1[p];
            a00 = ffma2(w0[2*p],   hp0.x, a00);
            a00 = ffma2(w0[2*p+1], hp0.y, a00);
            a01 = ffma2(w0[2*p],   hp1.x, a01);
            a01 = ffma2(w0[2*p+1], hp1.y, a01);
            a10 = ffma2(w1[2*p],   hp0.x, a10);
            a10 = ffma2(w1[2*p+1], hp0.y, a10);
            a11 = ffma2(w1[2*p],   hp1.x, a11);
            a11 = ffma2(w1[2*p+1], hp1.y, a11);
        }
        #pragma unroll
        for (int q = 0; q < KSM4; q++){
            float4 v0 = ws[q*NG + j0];
            float4 v1 = ws[q*NG + j1];
            ulonglong2 hq0 = h0[KREGP/2 + q];
            ulonglong2 hq1 = h1[KREGP/2 + q];
            ull w0a = pk2(v0.x, v0.y), w0b = pk2(v0.z, v0.w);
            ull w1a = pk2(v1.x, v1.y), w1b = pk2(v1.z, v1.w);
            a00 = ffma2(w0a, hq0.x, a00); a00 = ffma2(w0b, hq0.y, a00);
            a01 = ffma2(w0a, hq1.x, a01); a01 = ffma2(w0b, hq1.y, a01);
            a10 = ffma2(w1a, hq0.x, a10); a10 = ffma2(w1b, hq0.y, a10);
            a11 = ffma2(w1a, hq1.x, a11); a11 = ffma2(w1b, hq1.y, a11);
        }
        float2 f00 = unpk(a00), f01 = unpk(a01), f10 = unpk(a10), f11 = unpk(a11);
        float g00 = f00.x + f00.y, g01 = f01.x + f01.y;
        float g10 = f10.x + f10.y, g11 = f11.x + f11.y;
        g00 = sigf(g00); g01 = sigf(g01);
        if (tid < 128){ g10 = tanhf_(g10); g11 = tanhf_(g11); }
        else          { g10 = sigf(g10);   g11 = sigf(g11);  }
        sg[j0]      = g00; sg[j1]      = g10;
        sg[NG + j0] = g01; sg[NG + j1] = g11;
        __syncthreads();
        {
            int row = tid >> 7, u = tid & 127;
            float* cc = (tid < 128) ? &c0 : &c1;
            const float* sgr = sg + row * NG;
            float iv = sgr[u], fv = sgr[HID+u], gv = sgr[2*HID+u], ov = sgr[3*HID+u];
            *cc = fmaf(fv, *cc, iv * gv);
            float hv = ov * tanhf_(*cc);
            sh[row * HID + u] = hv;
            if (MODE != 2){
                g_hseq[((size_t)t * B_ROWS + r0 + row) * HID + u] = hv;
            } else if (t == T_STEPS - 1){
                g_hT[(size_t)(r0 + row) * HID + u] = hv;
            }
        }
        __syncthreads();
    }
}

// ================= input-projection GEMM v3 (frozen, measured 1.347ms) =======
constexpr int M_TILES   = (T_STEPS * B_ROWS) / 128;     // 4096
constexpr int GRID_X    = 37;
constexpr int A_TILE_F  = 128 * 128;
constexpr int BQ_F4     = 32 * 129;
constexpr int GEMM_SMEM = (2 * A_TILE_F) * 4 + BQ_F4 * 16;   // 197120 B

__global__ void __launch_bounds__(256, 1)
gemm_xg(const float* __restrict__ W,
        const float* __restrict__ ba,
        const float* __restrict__ bb)
{
    extern __shared__ float sm[];
    float*  As = sm;                             // [2][128][128]
    float4* Bq = (float4*)(sm + 2 * A_TILE_F);   // [32][129]

    const int tid = threadIdx.x;
    const int tx = tid & 15, ty = tid >> 4;
    const int n0 = blockIdx.y * 128;

    #pragma unroll
    for (int i = 0; i < 16; i++){
        int idx = tid + i * 256;                  // over [128 n][32 k4]
        int n = idx >> 5, k4 = idx & 31;
        Bq[k4 * 129 + n] = *(const float4*)&W[(size_t)(n0 + n) * HID + 4 * k4];
    }

    float bias[8];
    #pragma unroll
    for (int c = 0; c < 8; c++){
        int n = n0 + tx + 16*c;
        bias[c] = __ldg(ba + n) + __ldg(bb + n);
    }

    uint sA = (uint)__cvta_generic_to_shared(As);
    auto issue = [&](int mt, int buf){
        const float* src = g_hseq + (size_t)mt * A_TILE_F;
        uint dst = sA + buf * (A_TILE_F * 4);
        #pragma unroll
        for (int i = 0; i < 16; i++){
            int idx = tid + i * 256;
            asm volatile("cp.async.cg.shared.global [%0], [%1], 16;\n"
                         :: "r"(dst + idx * 16), "l"(src + idx * 4));
        }
        asm volatile("cp.async.commit_group;\n" ::: "memory");
    };

    int mt = blockIdx.x;
    if (mt < M_TILES) issue(mt, 0);
    int buf = 0;

    #pragma unroll 1
    for (; mt < M_TILES; mt += GRID_X){
        int nxt = mt + GRID_X;
        if (nxt < M_TILES) issue(nxt, buf ^ 1);
        if (nxt < M_TILES) asm volatile("cp.async.wait_group 1;\n" ::: "memory");
        else               asm volatile("cp.async.wait_group 0;\n" ::: "memory");
        __syncthreads();

        const float* Ab = As + buf * A_TILE_F;
        ull acc[8][8];
        #pragma unroll
        for (int r = 0; r < 8; r++)
            #pragma unroll
            for (int c = 0; c < 8; c++) acc[r][c] = 0ULL;

        #pragma unroll 1
        for (int kp2 = 0; kp2 < 32; kp2++){
            ulonglong2 a2[8], b2[8];
            #pragma unroll
            for (int r = 0; r < 8; r++)
                a2[r] = *(const ulonglong2*)&Ab[(ty*8 + r) * 128 + 4*kp2];
            #pragma unroll
            for (int c = 0; c < 8; c++)
                b2[c] = ((const ulonglong2*)Bq)[kp2 * 129 + tx + 16*c];
            #pragma unroll
            for (int r = 0; r < 8; r++)
                #pragma unroll
                for (int c = 0; c < 8; c++){
                    acc[r][c] = ffma2(a2[r].x, b2[c].x, acc[r][c]);
                    acc[r][c] = ffma2(a2[r].y, b2[c].y, acc[r][c]);
                }
        }

        #pragma unroll
        for (int c = 0; c < 8; c++){
            int n = tx + 16*c;
            #pragma unroll
            for (int r = 0; r < 8; r++){
                float2 v = unpk(acc[r][c]);
                g_xg[((size_t)mt * 128 + ty*8 + r) * NG + n0 + n] = v.x + v.y + bias[c];
            }
        }
        __syncthreads();
        buf ^= 1;
    }
}

// ================= FC head =================
__global__ void head_kernel(const float* __restrict__ w1, const float* __restrict__ b1,
                            const float* __restrict__ w2, const float* __restrict__ b2,
                            float* __restrict__ out)
{
    __shared__ float z[64];
    int b = blockIdx.x, u = threadIdx.x;
    const float* h = g_hT + (size_t)b * HID;
    float acc = b1[u];
    const float* w = w1 + (size_t)u * HID;
    #pragma unroll 4
    for (int k = 0; k < HID; k++) acc = fmaf(w[k], h[k], acc);
    z[u] = fmaxf(acc, 0.f);
    __syncthreads();
    if (u < 5){
        float a2 = b2[u];
        const float* ww = w2 + u * 64;
        #pragma unroll 4
        for (int k = 0; k < 64; k++) a2 = fmaf(ww[k], z[k], a2);
        out[b * 5 + u] = a2;
    }
}

// ================= launch =================
extern "C" void kernel_launch(void* const* d_in, const int* in_sizes, int n_in,
                              void* d_out, int out_size)
{
    const float* x    = (const float*)d_in[0];
    const float* Wih0 = (const float*)d_in[1];
    const float* Whh0 = (const float*)d_in[2];
    const float* bih0 = (const float*)d_in[3];
    const float* bhh0 = (const float*)d_in[4];
    const float* Wih1 = (const float*)d_in[5];
    const float* Whh1 = (const float*)d_in[6];
    const float* bih1 = (const float*)d_in[7];
    const float* bhh1 = (const float*)d_in[8];
    const float* Wih2 = (const float*)d_in[9];
    const float* Whh2 = (const float*)d_in[10];
    const float* bih2 = (const float*)d_in[11];
    const float* bhh2 = (const float*)d_in[12];
    const float* fc1w = (const float*)d_in[13];
    const float* fc1b = (const float*)d_in[14];
    const float* fc2w = (const float*)d_in[15];
    const float* fc2b = (const float*)d_in[16];
    float* out = (float*)d_out;

    cudaFuncSetAttribute(lstm_rec<0>, cudaFuncAttributeMaxDynamicSharedMemorySize, REC_SMEM0);
    cudaFuncSetAttribute(lstm_rec<1>, cudaFuncAttributeMaxDynamicSharedMemorySize, REC_SMEM_BASE);
    cudaFuncSetAttribute(lstm_rec<2>, cudaFuncAttributeMaxDynamicSharedMemorySize, REC_SMEM_BASE);
    cudaFuncSetAttribute(gemm_xg,     cudaFuncAttributeMaxDynamicSharedMemorySize, GEMM_SMEM);

    lstm_rec<0><<<128, 256, REC_SMEM0>>>(x, Wih0, bih0, bhh0, Whh0);
    gemm_xg<<<dim3(GRID_X, 4), 256, GEMM_SMEM>>>(Wih1, bih1, bhh1);
    lstm_rec<1><<<128, 256, REC_SMEM_BASE>>>(nullptr, nullptr, nullptr, nullptr, Whh1);
    gemm_xg<<<dim3(GRID_X, 4), 256, GEMM_SMEM>>>(Wih2, bih2, bhh2);
    lstm_rec<2><<<128, 256, REC_SMEM_BASE>>>(nullptr, nullptr, nullptr, nullptr, Whh2);
    head_kernel<<<B_ROWS, 64>>>(fc1w, fc1b, fc2w, fc2b, out);
}